// round 10
// baseline (speedup 1.0000x reference)
#include <cuda_runtime.h>
#include <math_constants.h>

#define D      128
#define BGR    512
#define NWARP  8
#define NTHR   256
#define KW     256          // GEMM K (= 2*D)
#define GCOLS  512          // GEMM output cols (4 gates x 128 features, interleaved)
#define STG    3            // per-warp cp.async ring depth
#define GRP    4            // nodes per stage

// init kernel block-range sizes
#define PREP_BLKS  512      // GCOLS*KW / 256
#define BIAS_BLKS  256      // BGR*D / 256

// ---------------- device scratch (no allocation allowed) ----------------
__device__ float g_h[BGR * D];            // hidden state (current)
__device__ float g_Wbig[GCOLS * KW];      // merged weights, col 4f+g, k over q_star
__device__ float g_bias[GCOLS];           // merged biases [br,bz,bin,bhn] per feature
__device__ int   g_starts[BGR + 1];       // segment boundaries (batch is sorted)

__device__ __forceinline__ float sigf(float v) {
    return 1.f / (1.f + __expf(-v));
}

__device__ __forceinline__ void cp16(void* sdst, const void* gsrc) {
    unsigned s = (unsigned)__cvta_generic_to_shared(sdst);
    asm volatile("cp.async.cg.shared.global [%0], [%1], 16;" :: "r"(s), "l"(gsrc));
}
__device__ __forceinline__ void cp_commit() {
    asm volatile("cp.async.commit_group;");
}
template<int N> __device__ __forceinline__ void cp_wait() {
    asm volatile("cp.async.wait_group %0;" :: "n"(N));
}

// batch may be delivered as int32 or int64; sniff layout from a mid element.
__device__ __forceinline__ bool batch_is_i64(const void* bp, int N) {
    long long v = ((const long long*)bp)[N >> 2];
    return (v >= 0 && v < BGR);
}
__device__ __forceinline__ int batch_at(const void* bp, int i, bool is64) {
    int v = is64 ? (int)((const long long*)bp)[i] : ((const int*)bp)[i];
    return min(max(v, 0), BGR - 1);
}

// ---------------- fused init: prep (Wbig/bias) + step-1 h + segment starts -------------
// blocks [0,512): weight merge; [512,768): bias-only GRU step-1 h; [768,...): starts.
__global__ void init_kernel(const void* __restrict__ batch, int N,
                            const float* __restrict__ W_ih, const float* __restrict__ W_hh,
                            const float* __restrict__ b_ih, const float* __restrict__ b_hh) {
    int bx = blockIdx.x;
    int t  = threadIdx.x;

    if (bx < PREP_BLKS) {
        // ---- weight/bias merge: col c = 4f+g over k in [0,KW) ----
        int idx = bx * 256 + t;                 // < GCOLS*KW
        int c = idx >> 8;
        int k = idx & (KW - 1);
        int f = c >> 2, g = c & 3;
        float v;
        if (g == 0)      v = W_ih[(size_t)f * KW + k]         + (k < D ? W_hh[(size_t)f * D + k] : 0.f);
        else if (g == 1) v = W_ih[(size_t)(D + f) * KW + k]   + (k < D ? W_hh[(size_t)(D + f) * D + k] : 0.f);
        else if (g == 2) v = W_ih[(size_t)(2 * D + f) * KW + k];
        else             v = (k < D) ? W_hh[(size_t)(2 * D + f) * D + k] : 0.f;
        g_Wbig[(size_t)c * KW + k] = v;
        if (k == 0) {
            float b;
            if (g == 0)      b = b_ih[f] + b_hh[f];
            else if (g == 1) b = b_ih[D + f] + b_hh[D + f];
            else if (g == 2) b = b_ih[2 * D + f];
            else             b = b_hh[2 * D + f];
            g_bias[c] = b;
        }
    } else if (bx < PREP_BLKS + BIAS_BLKS) {
        // ---- step-1 GRU: h = f(biases) (h=0, q_star=0) ----
        int idx = (bx - PREP_BLKS) * 256 + t;   // < BGR*D
        int f = idx & (D - 1);
        float r = sigf(b_ih[f] + b_hh[f]);
        float z = sigf(b_ih[D + f] + b_hh[D + f]);
        float n = tanhf(b_ih[2 * D + f] + r * b_hh[2 * D + f]);
        g_h[idx] = (1.f - z) * n;
    } else {
        // ---- segment boundaries from sorted batch ----
        int i = (bx - PREP_BLKS - BIAS_BLKS) * 256 + t;
        if (i >= N) return;
        bool is64 = batch_is_i64(batch, N);
        int bi = batch_at(batch, i, is64);
        if (i == 0) {
            for (int b = 0; b <= bi; b++) g_starts[b] = 0;
        } else {
            int bp = batch_at(batch, i - 1, is64);
            for (int b = bp + 1; b <= bi; b++) g_starts[b] = i;
        }
        if (i == N - 1) {
            for (int b = bi + 1; b <= BGR; b++) g_starts[b] = N;
        }
    }
}

// ---------------- whole GRU step as ONE register-tiled GEMM with gate epilogue ----------
// C[512 x 512] = q_star[512 x 256] @ Wbig^T ; block tile 16 rows x 64 cols (16 features),
// grid (8, 32) = 256 blocks, 128 threads, thread tile 2x4. Epilogue writes h into g_h.
#define GKT 16
__global__ void __launch_bounds__(128) gru_fused_kernel(const float* __restrict__ q_star) {
    __shared__ __align__(16) float As[GKT][16];
    __shared__ __align__(16) float Ws[GKT][64];

    int t  = threadIdx.x;
    int tx = t & 15;           // feature within tile
    int ty = t >> 4;           // 0..7 -> rows ty and ty+8
    int r0 = blockIdx.y * 16;
    int c0 = blockIdx.x * 64;

    float acc[2][4] = {};

    for (int k0 = 0; k0 < KW; k0 += GKT) {
        if (t < 64) {          // A tile 16r x 16k: row = t>>2, k=(t&3)*4
            int row = t >> 2, k = (t & 3) << 2;
            float4 v = *(const float4*)(q_star + (size_t)(r0 + row) * KW + k0 + k);
            As[k][row] = v.x; As[k + 1][row] = v.y; As[k + 2][row] = v.z; As[k + 3][row] = v.w;
        }
        {   // W tile 64c x 16k: col = t>>1, k = (t&1)*8 (two float4)
            int col = t >> 1, k = (t & 1) << 3;
            const float* wp = g_Wbig + (size_t)(c0 + col) * KW + k0 + k;
            float4 v0 = *(const float4*)wp;
            float4 v1 = *(const float4*)(wp + 4);
            Ws[k][col]     = v0.x; Ws[k + 1][col] = v0.y; Ws[k + 2][col] = v0.z; Ws[k + 3][col] = v0.w;
            Ws[k + 4][col] = v1.x; Ws[k + 5][col] = v1.y; Ws[k + 6][col] = v1.z; Ws[k + 7][col] = v1.w;
        }
        __syncthreads();
#pragma unroll
        for (int kk = 0; kk < GKT; kk++) {
            float a0 = As[kk][ty], a1 = As[kk][ty + 8];
            float w[4];
            *(float4*)w = *(const float4*)&Ws[kk][tx * 4];
#pragma unroll
            for (int j = 0; j < 4; j++) {
                acc[0][j] += a0 * w[j];
                acc[1][j] += a1 * w[j];
            }
        }
        __syncthreads();
    }

    int f = (c0 >> 2) + tx;
    float4 gb = *(const float4*)&g_bias[4 * f];   // [br, bz, bin, bhn]
#pragma unroll
    for (int i = 0; i < 2; i++) {
        int row = r0 + ty + i * 8;
        float hold = q_star[(size_t)row * KW + f];    // h_old = q half of q_star
        float r = sigf(acc[i][0] + gb.x);
        float z = sigf(acc[i][1] + gb.y);
        float n = tanhf(acc[i][2] + gb.z + r * (acc[i][3] + gb.w));
        g_h[(size_t)row * D + f] = (1.f - z) * n + z * hold;
    }
}

// ---------------- fused segment attention: PER-WARP cp.async ring (no block barriers) ----
// block b owns graph b; warp w owns node groups {start + 4w + 32k}. Each warp runs a
// private 3-stage cp.async pipeline into its own smem slice; only __syncwarp inside loop.
__global__ void __launch_bounds__(NTHR) attn_kernel(const float* __restrict__ x,
                                                    float* __restrict__ q_star) {
    __shared__ __align__(16) float xs[NWARP][STG][GRP][D];   // 48KB
    __shared__ __align__(16) float q_s[D];
    __shared__ float wm[NWARP], wsum[NWARP];
    __shared__ __align__(16) float wr[NWARP][D];

    int b = blockIdx.x;
    int start = g_starts[b];
    int end   = g_starts[b + 1];
    int t = threadIdx.x;
    int warp = t >> 5;
    int lane = t & 31;

    if (t < D) {
        float qv = g_h[(size_t)b * D + t];
        q_s[t] = qv;
        q_star[(size_t)b * (2 * D) + t] = qv;   // q half (always)
    }
    __syncthreads();

    if (start >= end) {                 // empty graph: r = 0
        if (t < D) q_star[(size_t)b * (2 * D) + D + t] = 0.f;
        return;
    }

    const int stride = NWARP * GRP;     // 32
    int base0 = start + warp * GRP;
    int last  = end - 1;
    int ngrp  = (base0 < end) ? (end - base0 + stride - 1) / stride : 0;

    // prologue: issue STG groups (commit even when empty to keep group counts aligned)
#pragma unroll
    for (int i = 0; i < STG; i++) {
        int gbase = base0 + i * stride;
        if (i < ngrp) {
#pragma unroll
            for (int j = 0; j < GRP; j++) {
                int node = min(gbase + j, last);
                cp16(&xs[warp][i][j][lane * 4], x + (size_t)node * D + lane * 4);
            }
        }
        cp_commit();
    }

    float4 qf = *(const float4*)(q_s + lane * 4);
    float m = -CUDART_INF_F;
    float s = 0.f;
    float4 racc = make_float4(0.f, 0.f, 0.f, 0.f);

    for (int gi = 0; gi < ngrp; gi++) {
        cp_wait<STG - 1>();             // group gi resident (per-thread state)
        __syncwarp();                   // cross-lane smem visibility within warp

        int slot = gi % STG;
        int gbase = base0 + gi * stride;
        float4 xv[GRP];
        float  d[GRP];
#pragma unroll
        for (int j = 0; j < GRP; j++) {
            xv[j] = *(const float4*)&xs[warp][slot][j][lane * 4];
            d[j] = xv[j].x * qf.x + xv[j].y * qf.y + xv[j].z * qf.z + xv[j].w * qf.w;
        }
#pragma unroll
        for (int off = 16; off >= 1; off >>= 1) {
#pragma unroll
            for (int j = 0; j < GRP; j++) d[j] += __shfl_xor_sync(0xffffffffu, d[j], off);
        }
#pragma unroll
        for (int j = 0; j < GRP; j++) {
            if (gbase + j >= end) break;           // warp-uniform; pads never touch m
            if (d[j] <= m) {
                float w = __expf(d[j] - m);
                s += w;
                racc.x += w * xv[j].x; racc.y += w * xv[j].y;
                racc.z += w * xv[j].z; racc.w += w * xv[j].w;
            } else {                               // new max (always on warp's first node)
                float sc = __expf(m - d[j]);       // 0 when m=-inf
                m = d[j];
                s = s * sc + 1.f;
                racc.x = racc.x * sc + xv[j].x; racc.y = racc.y * sc + xv[j].y;
                racc.z = racc.z * sc + xv[j].z; racc.w = racc.w * sc + xv[j].w;
            }
        }
        __syncwarp();                   // all lanes done reading slot before refill

        int nb = base0 + (gi + STG) * stride;      // refill slot with group gi+STG
        if (gi + STG < ngrp) {
#pragma unroll
            for (int j = 0; j < GRP; j++) {
                int node = min(nb + j, last);
                cp16(&xs[warp][slot][j][lane * 4], x + (size_t)node * D + lane * 4);
            }
        }
        cp_commit();
    }

    if (lane == 0) { wm[warp] = m; wsum[warp] = s; }
    *(float4*)(&wr[warp][lane * 4]) = racc;
    __syncthreads();

    if (t < D) {
        float mb = wm[0];
#pragma unroll
        for (int w = 1; w < NWARP; w++) mb = fmaxf(mb, wm[w]);
        float stot = 0.f, rf = 0.f;
#pragma unroll
        for (int w = 0; w < NWARP; w++) {
            float c = __expf(wm[w] - mb);   // 0 for warps that saw no node (wm=-inf)
            stot += c * wsum[w];
            rf   += c * wr[w][t];
        }
        q_star[(size_t)b * (2 * D) + D + t] = rf / (stot + 1e-16f);
    }
}

// ---------------- launch ----------------
extern "C" void kernel_launch(void* const* d_in, const int* in_sizes, int n_in,
                              void* d_out, int out_size) {
    const float* x     = (const float*)d_in[0];
    const void*  batch = d_in[1];
    int base = (n_in >= 7) ? 3 : 2;    // d_in[2] may be the batch_size scalar
    const float* W_ih = (const float*)d_in[base];
    const float* W_hh = (const float*)d_in[base + 1];
    const float* b_ih = (const float*)d_in[base + 2];
    const float* b_hh = (const float*)d_in[base + 3];

    float* q_star = (float*)d_out;     // [BGR, 2D]
    int N = in_sizes[0] / D;

    // one fused init launch: prep + step-1 h + starts
    int init_blocks = PREP_BLKS + BIAS_BLKS + (N + 255) / 256;
    init_kernel<<<init_blocks, 256>>>(batch, N, W_ih, W_hh, b_ih, b_hh);

    dim3 ggrid(GCOLS / 64, BGR / 16);  // 8 x 32 = 256 blocks for the fused GRU GEMM

    attn_kernel<<<BGR, NTHR>>>(x, q_star);

    gru_fused_kernel<<<ggrid, 128>>>(q_star);
    attn_kernel<<<BGR, NTHR>>>(x, q_star);

    gru_fused_kernel<<<ggrid, 128>>>(q_star);
    attn_kernel<<<BGR, NTHR>>>(x, q_star);
}

// round 11
// speedup vs baseline: 1.1343x; 1.1343x over previous
#include <cuda_runtime.h>
#include <math_constants.h>

#define D      128
#define BGR    512
#define NWARP  8
#define NTHR   256
#define KW     256          // GEMM K (= 2*D)
#define GCOLS  512          // GEMM output cols (4 gates x 128 features, interleaved)
#define STG    3            // per-warp cp.async ring depth
#define GRP    4            // nodes per stage
#define GRUA_BLKS 64        // embedded h-half GEMM blocks (64x64 tiles)

// init kernel block-range sizes
#define PREP_BLKS  512      // GCOLS*KW / 256
#define BIAS_BLKS  256      // BGR*D / 256

// ---------------- device scratch (no allocation allowed) ----------------
__device__ float g_h[BGR * D];            // hidden state (current)
__device__ float g_Wbig[GCOLS * KW];      // merged weights, col 4f+g, k over q_star
__device__ float g_bias[GCOLS];           // merged biases [br,bz,bin,bhn] per feature
__device__ int   g_starts[BGR + 1];       // segment boundaries (batch is sorted)
__device__ float g_acc[BGR * GCOLS];      // h-half GEMM partial accumulators (1MB)

__device__ __forceinline__ float sigf(float v) {
    return 1.f / (1.f + __expf(-v));
}

__device__ __forceinline__ void cp16(void* sdst, const void* gsrc) {
    unsigned s = (unsigned)__cvta_generic_to_shared(sdst);
    asm volatile("cp.async.cg.shared.global [%0], [%1], 16;" :: "r"(s), "l"(gsrc));
}
__device__ __forceinline__ void cp_commit() {
    asm volatile("cp.async.commit_group;");
}
template<int N> __device__ __forceinline__ void cp_wait() {
    asm volatile("cp.async.wait_group %0;" :: "n"(N));
}

// batch may be delivered as int32 or int64; sniff layout from a mid element.
__device__ __forceinline__ bool batch_is_i64(const void* bp, int N) {
    long long v = ((const long long*)bp)[N >> 2];
    return (v >= 0 && v < BGR);
}
__device__ __forceinline__ int batch_at(const void* bp, int i, bool is64) {
    int v = is64 ? (int)((const long long*)bp)[i] : ((const int*)bp)[i];
    return min(max(v, 0), BGR - 1);
}

// ---------------- fused init: prep (Wbig/bias) + step-1 h + segment starts -------------
__global__ void init_kernel(const void* __restrict__ batch, int N,
                            const float* __restrict__ W_ih, const float* __restrict__ W_hh,
                            const float* __restrict__ b_ih, const float* __restrict__ b_hh) {
    int bx = blockIdx.x;
    int t  = threadIdx.x;

    if (bx < PREP_BLKS) {
        int idx = bx * 256 + t;                 // < GCOLS*KW
        int c = idx >> 8;
        int k = idx & (KW - 1);
        int f = c >> 2, g = c & 3;
        float v;
        if (g == 0)      v = W_ih[(size_t)f * KW + k]         + (k < D ? W_hh[(size_t)f * D + k] : 0.f);
        else if (g == 1) v = W_ih[(size_t)(D + f) * KW + k]   + (k < D ? W_hh[(size_t)(D + f) * D + k] : 0.f);
        else if (g == 2) v = W_ih[(size_t)(2 * D + f) * KW + k];
        else             v = (k < D) ? W_hh[(size_t)(2 * D + f) * D + k] : 0.f;
        g_Wbig[(size_t)c * KW + k] = v;
        if (k == 0) {
            float b;
            if (g == 0)      b = b_ih[f] + b_hh[f];
            else if (g == 1) b = b_ih[D + f] + b_hh[D + f];
            else if (g == 2) b = b_ih[2 * D + f];
            else             b = b_hh[2 * D + f];
            g_bias[c] = b;
        }
    } else if (bx < PREP_BLKS + BIAS_BLKS) {
        int idx = (bx - PREP_BLKS) * 256 + t;   // < BGR*D
        int f = idx & (D - 1);
        float r = sigf(b_ih[f] + b_hh[f]);
        float z = sigf(b_ih[D + f] + b_hh[D + f]);
        float n = tanhf(b_ih[2 * D + f] + r * b_hh[2 * D + f]);
        g_h[idx] = (1.f - z) * n;
    } else {
        int i = (bx - PREP_BLKS - BIAS_BLKS) * 256 + t;
        if (i >= N) return;
        bool is64 = batch_is_i64(batch, N);
        int bi = batch_at(batch, i, is64);
        if (i == 0) {
            for (int b = 0; b <= bi; b++) g_starts[b] = 0;
        } else {
            int bp = batch_at(batch, i - 1, is64);
            for (int b = bp + 1; b <= bi; b++) g_starts[b] = i;
        }
        if (i == N - 1) {
            for (int b = bi + 1; b <= BGR; b++) g_starts[b] = N;
        }
    }
}

// ---------------- gruB: r-half GEMM + gate epilogue (critical path) --------------------
// acc[512x512] += q_star[:,128:256] @ Wbig[:,128:256]^T, then GRU gates -> g_h.
// 32 rows x 64 cols tiles, grid (8,16) = 128 blocks, 128 threads, 4x4 thread tile.
#define GKT 16
__global__ void __launch_bounds__(128) grub_kernel(const float* __restrict__ q_star) {
    __shared__ __align__(16) float As[GKT][32];
    __shared__ __align__(16) float Ws[GKT][64];

    int t  = threadIdx.x;
    int tx = t & 15;
    int ty = t >> 4;           // 0..7 -> 4 rows each
    int r0 = blockIdx.y * 32;
    int c0 = blockIdx.x * 64;

    float acc[4][4];
#pragma unroll
    for (int i = 0; i < 4; i++)
        *(float4*)acc[i] = *(const float4*)(g_acc + (size_t)(r0 + ty * 4 + i) * GCOLS + c0 + tx * 4);

    for (int k0 = 0; k0 < D; k0 += GKT) {
        {   // A tile 32r x 16k from q_star r-half
            int row = t >> 2, k = (t & 3) << 2;
            float4 v = *(const float4*)(q_star + (size_t)(r0 + row) * KW + D + k0 + k);
            As[k][row] = v.x; As[k + 1][row] = v.y; As[k + 2][row] = v.z; As[k + 3][row] = v.w;
        }
        {   // W tile 64c x 16k from Wbig k in [128,256)
            int col = t >> 1, k = (t & 1) << 3;
            const float* wp = g_Wbig + (size_t)(c0 + col) * KW + D + k0 + k;
            float4 v0 = *(const float4*)wp;
            float4 v1 = *(const float4*)(wp + 4);
            Ws[k][col]     = v0.x; Ws[k + 1][col] = v0.y; Ws[k + 2][col] = v0.z; Ws[k + 3][col] = v0.w;
            Ws[k + 4][col] = v1.x; Ws[k + 5][col] = v1.y; Ws[k + 6][col] = v1.z; Ws[k + 7][col] = v1.w;
        }
        __syncthreads();
#pragma unroll
        for (int kk = 0; kk < GKT; kk++) {
            float a[4], w[4];
            *(float4*)a = *(const float4*)&As[kk][ty * 4];
            *(float4*)w = *(const float4*)&Ws[kk][tx * 4];
#pragma unroll
            for (int i = 0; i < 4; i++) {
#pragma unroll
                for (int j = 0; j < 4; j++) acc[i][j] += a[i] * w[j];
            }
        }
        __syncthreads();
    }

    int f = (c0 >> 2) + tx;
    float4 gb = *(const float4*)&g_bias[4 * f];   // [br, bz, bin, bhn]
#pragma unroll
    for (int i = 0; i < 4; i++) {
        int row = r0 + ty * 4 + i;
        float hold = q_star[(size_t)row * KW + f];    // h_old = q half of q_star
        float r = sigf(acc[i][0] + gb.x);
        float z = sigf(acc[i][1] + gb.y);
        float n = tanhf(acc[i][2] + gb.z + r * (acc[i][3] + gb.w));
        g_h[(size_t)row * D + f] = (1.f - z) * n + z * hold;
    }
}

// ---------------- attention (per-warp cp.async ring) + embedded h-half GEMM ------------
// blocks [0,512): attention for graph b. blocks [512,576): gruA — g_acc = h @ Wh^T
// (64x64 tiles, 16x16 threads, 4x4 each) for the NEXT GRU step; runs on FMA pipes
// that attention leaves idle. Grid 576 <= 592 co-residency -> full overlap.
__global__ void __launch_bounds__(NTHR) attn_kernel(const float* __restrict__ x,
                                                    float* __restrict__ q_star) {
    __shared__ __align__(16) float xs[NWARP][STG][GRP][D];   // 48KB (aliased by gruA)
    __shared__ __align__(16) float q_s[D];
    __shared__ float wm[NWARP], wsum[NWARP];
    __shared__ __align__(16) float wr[NWARP][D];

    int t = threadIdx.x;

    if (blockIdx.x >= BGR) {
        // ---------- gruA: acc = h @ Wbig[:, :128]^T into g_acc ----------
        int gb = blockIdx.x - BGR;
        int r0 = (gb & 7) * 64;
        int c0 = (gb >> 3) * 64;
        float* As = (float*)xs;          // [16][64]
        float* Ws = As + GKT * 64;       // [16][64]
        int tx = t & 15, ty = t >> 4;    // 16x16 threads, 4x4 each
        float acc[4][4] = {};

        for (int k0 = 0; k0 < D; k0 += GKT) {
            {   // A tile 64r x 16k from g_h
                int row = t >> 2, k = (t & 3) << 2;
                float4 v = *(const float4*)(g_h + (size_t)(r0 + row) * D + k0 + k);
                As[(k) * 64 + row]     = v.x;
                As[(k + 1) * 64 + row] = v.y;
                As[(k + 2) * 64 + row] = v.z;
                As[(k + 3) * 64 + row] = v.w;
            }
            {   // W tile 64c x 16k from Wbig k in [0,128)
                int col = t >> 2, k = (t & 3) << 2;
                float4 v = *(const float4*)(g_Wbig + (size_t)(c0 + col) * KW + k0 + k);
                Ws[(k) * 64 + col]     = v.x;
                Ws[(k + 1) * 64 + col] = v.y;
                Ws[(k + 2) * 64 + col] = v.z;
                Ws[(k + 3) * 64 + col] = v.w;
            }
            __syncthreads();
#pragma unroll
            for (int kk = 0; kk < GKT; kk++) {
                float a[4], w[4];
                *(float4*)a = *(const float4*)&As[kk * 64 + ty * 4];
                *(float4*)w = *(const float4*)&Ws[kk * 64 + tx * 4];
#pragma unroll
                for (int i = 0; i < 4; i++) {
#pragma unroll
                    for (int j = 0; j < 4; j++) acc[i][j] += a[i] * w[j];
                }
            }
            __syncthreads();
        }
#pragma unroll
        for (int i = 0; i < 4; i++)
            *(float4*)(g_acc + (size_t)(r0 + ty * 4 + i) * GCOLS + c0 + tx * 4) = *(float4*)acc[i];
        return;
    }

    // ---------- attention ----------
    int b = blockIdx.x;
    int start = g_starts[b];
    int end   = g_starts[b + 1];
    int warp = t >> 5;
    int lane = t & 31;

    if (t < D) {
        float qv = g_h[(size_t)b * D + t];
        q_s[t] = qv;
        q_star[(size_t)b * (2 * D) + t] = qv;   // q half (always)
    }
    __syncthreads();

    if (start >= end) {                 // empty graph: r = 0
        if (t < D) q_star[(size_t)b * (2 * D) + D + t] = 0.f;
        return;
    }

    const int stride = NWARP * GRP;     // 32
    int base0 = start + warp * GRP;
    int last  = end - 1;
    int ngrp  = (base0 < end) ? (end - base0 + stride - 1) / stride : 0;

#pragma unroll
    for (int i = 0; i < STG; i++) {
        int gbase = base0 + i * stride;
        if (i < ngrp) {
#pragma unroll
            for (int j = 0; j < GRP; j++) {
                int node = min(gbase + j, last);
                cp16(&xs[warp][i][j][lane * 4], x + (size_t)node * D + lane * 4);
            }
        }
        cp_commit();
    }

    float4 qf = *(const float4*)(q_s + lane * 4);
    float m = -CUDART_INF_F;
    float s = 0.f;
    float4 racc = make_float4(0.f, 0.f, 0.f, 0.f);

    for (int gi = 0; gi < ngrp; gi++) {
        cp_wait<STG - 1>();
        __syncwarp();

        int slot = gi % STG;
        int gbase = base0 + gi * stride;
        float4 xv[GRP];
        float  d[GRP];
#pragma unroll
        for (int j = 0; j < GRP; j++) {
            xv[j] = *(const float4*)&xs[warp][slot][j][lane * 4];
            d[j] = xv[j].x * qf.x + xv[j].y * qf.y + xv[j].z * qf.z + xv[j].w * qf.w;
        }
#pragma unroll
        for (int off = 16; off >= 1; off >>= 1) {
#pragma unroll
            for (int j = 0; j < GRP; j++) d[j] += __shfl_xor_sync(0xffffffffu, d[j], off);
        }
#pragma unroll
        for (int j = 0; j < GRP; j++) {
            if (gbase + j >= end) break;           // warp-uniform; pads never touch m
            if (d[j] <= m) {
                float w = __expf(d[j] - m);
                s += w;
                racc.x += w * xv[j].x; racc.y += w * xv[j].y;
                racc.z += w * xv[j].z; racc.w += w * xv[j].w;
            } else {
                float sc = __expf(m - d[j]);       // 0 when m=-inf
                m = d[j];
                s = s * sc + 1.f;
                racc.x = racc.x * sc + xv[j].x; racc.y = racc.y * sc + xv[j].y;
                racc.z = racc.z * sc + xv[j].z; racc.w = racc.w * sc + xv[j].w;
            }
        }
        __syncwarp();

        int nb = base0 + (gi + STG) * stride;
        if (gi + STG < ngrp) {
#pragma unroll
            for (int j = 0; j < GRP; j++) {
                int node = min(nb + j, last);
                cp16(&xs[warp][slot][j][lane * 4], x + (size_t)node * D + lane * 4);
            }
        }
        cp_commit();
    }

    if (lane == 0) { wm[warp] = m; wsum[warp] = s; }
    *(float4*)(&wr[warp][lane * 4]) = racc;
    __syncthreads();

    if (t < D) {
        float mb = wm[0];
#pragma unroll
        for (int w = 1; w < NWARP; w++) mb = fmaxf(mb, wm[w]);
        float stot = 0.f, rf = 0.f;
#pragma unroll
        for (int w = 0; w < NWARP; w++) {
            float c = __expf(wm[w] - mb);   // 0 for warps that saw no node (wm=-inf)
            stot += c * wsum[w];
            rf   += c * wr[w][t];
        }
        q_star[(size_t)b * (2 * D) + D + t] = rf / (stot + 1e-16f);
    }
}

// ---------------- launch ----------------
extern "C" void kernel_launch(void* const* d_in, const int* in_sizes, int n_in,
                              void* d_out, int out_size) {
    const float* x     = (const float*)d_in[0];
    const void*  batch = d_in[1];
    int base = (n_in >= 7) ? 3 : 2;    // d_in[2] may be the batch_size scalar
    const float* W_ih = (const float*)d_in[base];
    const float* W_hh = (const float*)d_in[base + 1];
    const float* b_ih = (const float*)d_in[base + 2];
    const float* b_hh = (const float*)d_in[base + 3];

    float* q_star = (float*)d_out;     // [BGR, 2D]
    int N = in_sizes[0] / D;

    int init_blocks = PREP_BLKS + BIAS_BLKS + (N + 255) / 256;
    init_kernel<<<init_blocks, 256>>>(batch, N, W_ih, W_hh, b_ih, b_hh);

    dim3 bgrid(GCOLS / 64, BGR / 32);  // 8 x 16 = 128 blocks for gruB

    // pass k: attention (blocks 0..511) + h-half GEMM for step k+1 (blocks 512..575)
    attn_kernel<<<BGR + GRUA_BLKS, NTHR>>>(x, q_star);
    grub_kernel<<<bgrid, 128>>>(q_star);

    attn_kernel<<<BGR + GRUA_BLKS, NTHR>>>(x, q_star);
    grub_kernel<<<bgrid, 128>>>(q_star);

    attn_kernel<<<BGR + GRUA_BLKS, NTHR>>>(x, q_star);
}